// round 7
// baseline (speedup 1.0000x reference)
#include <cuda_runtime.h>
#include <cuda_fp16.h>
#include <cstdint>

#define N_NODES   50000
#define N_EDGES   800000
#define IN_FEATS  256
#define OUT_FEATS 64
#define CAP       64    // max degree capacity; P(Poisson(16) > 64) ~ 2e-18/node

// Scratch (__device__ globals: no allocation allowed)
__device__ __half   g_hw_h[N_NODES * OUT_FEATS];    // (h@W)*norm in fp16, 6.4MB
__device__ uint32_t g_w_tf32[IN_FEATS * OUT_FEATS]; // W pre-converted to tf32
__device__ int      g_cnt[N_NODES];                 // per-dst degree counters
__device__ int      g_esrc[N_NODES * CAP];          // bucketed src ids (12.8MB)

// ---------------------------------------------------------------------------
// Kernel 0: convert W -> tf32 (rna) once.
// ---------------------------------------------------------------------------
__global__ __launch_bounds__(256)
void wconv_kernel(const float* __restrict__ W) {
    int gid = blockIdx.x * blockDim.x + threadIdx.x;   // 4096 float4s
    if (gid < IN_FEATS * OUT_FEATS / 4) {
        float4 v = *reinterpret_cast<const float4*>(W + gid * 4);
        uint4 u;
        asm("cvt.rna.tf32.f32 %0, %1;" : "=r"(u.x) : "f"(v.x));
        asm("cvt.rna.tf32.f32 %0, %1;" : "=r"(u.y) : "f"(v.y));
        asm("cvt.rna.tf32.f32 %0, %1;" : "=r"(u.z) : "f"(v.z));
        asm("cvt.rna.tf32.f32 %0, %1;" : "=r"(u.w) : "f"(v.w));
        *reinterpret_cast<uint4*>(g_w_tf32 + gid * 4) = u;
    }
}

// ---------------------------------------------------------------------------
// Kernel 1: zero the degree counters
// ---------------------------------------------------------------------------
__global__ __launch_bounds__(256)
void zero_cnt_kernel() {
    int gid = blockIdx.x * blockDim.x + threadIdx.x;
    if (gid < N_NODES) g_cnt[gid] = 0;
}

// ---------------------------------------------------------------------------
// Kernel 2: hw = (h @ W) * norm  -- tf32 mma.sync, cp.async double-buffered.
// Tile: 128 rows x 64 cols, BK=64, 256 threads. Output stored as fp16.
// ---------------------------------------------------------------------------
#define PAD_A 68
#define PAD_B 72

__device__ __forceinline__ uint32_t f2tf32(float f) {
    uint32_t u;
    asm("cvt.rna.tf32.f32 %0, %1;" : "=r"(u) : "f"(f));
    return u;
}

__device__ __forceinline__ void cp_async16(void* smem_dst, const void* gmem_src) {
    uint32_t s;
    asm("{ .reg .u64 t; cvta.to.shared.u64 t, %1; cvt.u32.u64 %0, t; }"
        : "=r"(s) : "l"(smem_dst));
    asm volatile("cp.async.cg.shared.global [%0], [%1], 16;" :: "r"(s), "l"(gmem_src));
}

__global__ __launch_bounds__(256)
void gemm_tf32_kernel(const float* __restrict__ h,
                      const float* __restrict__ norm) {
    __shared__ uint32_t shA[2][128 * PAD_A];   // raw fp32 bits
    __shared__ uint32_t shB[2][64 * PAD_B];    // tf32 bits

    const int tid  = threadIdx.x;
    const int warp = tid >> 5;
    const int lane = tid & 31;
    const int g    = lane >> 2;   // 0..7
    const int tg   = lane & 3;    // 0..3
    const int rowBase = blockIdx.x * 128;

    float acc[8][4];
    #pragma unroll
    for (int t = 0; t < 8; t++)
        #pragma unroll
        for (int i = 0; i < 4; i++) acc[t][i] = 0.f;

    auto stage = [&](int kk, int b) {
        #pragma unroll
        for (int j = 0; j < 8; j++) {                  // A: 2048 float4 / 256 thr
            int idx = tid + j * 256;
            int r   = idx >> 4;
            int k4  = idx & 15;
            int row = rowBase + r;
            if (row >= N_NODES) row = N_NODES - 1;     // clamp: junk computed, never stored
            cp_async16(&shA[b][r * PAD_A + k4 * 4],
                       h + (size_t)row * IN_FEATS + kk + k4 * 4);
        }
        #pragma unroll
        for (int j = 0; j < 4; j++) {                  // B: 1024 float4 / 256 thr
            int idx = tid + j * 256;
            int r   = idx >> 4;
            int k4  = idx & 15;
            cp_async16(&shB[b][r * PAD_B + k4 * 4],
                       g_w_tf32 + (size_t)(kk + r) * OUT_FEATS + k4 * 4);
        }
        asm volatile("cp.async.commit_group;" ::: "memory");
    };

    stage(0, 0);

    #pragma unroll
    for (int c = 0; c < 4; c++) {                      // 4 K-chunks of 64
        if (c < 3) stage((c + 1) * 64, (c + 1) & 1);
        if (c < 3) asm volatile("cp.async.wait_group 1;" ::: "memory");
        else       asm volatile("cp.async.wait_group 0;" ::: "memory");
        __syncthreads();

        const uint32_t* A = shA[c & 1];
        const uint32_t* B = shB[c & 1];
        const int ar = warp * 16;
        #pragma unroll
        for (int k8 = 0; k8 < 64; k8 += 8) {
            uint32_t a0 = f2tf32(__uint_as_float(A[(ar + g    ) * PAD_A + k8 + tg    ]));
            uint32_t a1 = f2tf32(__uint_as_float(A[(ar + g + 8) * PAD_A + k8 + tg    ]));
            uint32_t a2 = f2tf32(__uint_as_float(A[(ar + g    ) * PAD_A + k8 + tg + 4]));
            uint32_t a3 = f2tf32(__uint_as_float(A[(ar + g + 8) * PAD_A + k8 + tg + 4]));
            #pragma unroll
            for (int t = 0; t < 8; t++) {
                uint32_t b0 = B[(k8 + tg    ) * PAD_B + t * 8 + g];
                uint32_t b1 = B[(k8 + tg + 4) * PAD_B + t * 8 + g];
                asm volatile(
                    "mma.sync.aligned.m16n8k8.row.col.f32.tf32.tf32.f32 "
                    "{%0,%1,%2,%3}, {%4,%5,%6,%7}, {%8,%9}, {%0,%1,%2,%3};"
                    : "+f"(acc[t][0]), "+f"(acc[t][1]), "+f"(acc[t][2]), "+f"(acc[t][3])
                    : "r"(a0), "r"(a1), "r"(a2), "r"(a3), "r"(b0), "r"(b1));
            }
        }
        __syncthreads();
    }

    int r0 = rowBase + warp * 16 + g;
    int r1 = r0 + 8;
    if (r0 < N_NODES) {
        float nv = norm[r0];
        #pragma unroll
        for (int t = 0; t < 8; t++) {
            __half2 p = __floats2half2_rn(acc[t][0] * nv, acc[t][1] * nv);
            *reinterpret_cast<__half2*>(g_hw_h + (size_t)r0 * OUT_FEATS + t * 8 + tg * 2) = p;
        }
    }
    if (r1 < N_NODES) {
        float nv = norm[r1];
        #pragma unroll
        for (int t = 0; t < 8; t++) {
            __half2 p = __floats2half2_rn(acc[t][2] * nv, acc[t][3] * nv);
            *reinterpret_cast<__half2*>(g_hw_h + (size_t)r1 * OUT_FEATS + t * 8 + tg * 2) = p;
        }
    }
}

// ---------------------------------------------------------------------------
// Kernel 3: bucket placement, 1 edge per thread.
// ---------------------------------------------------------------------------
__global__ __launch_bounds__(256)
void place_kernel(const int* __restrict__ src, const int* __restrict__ dst) {
    int e = blockIdx.x * blockDim.x + threadIdx.x;
    if (e < N_EDGES) {
        int d = __ldg(dst + e);
        int s = __ldg(src + e);
        int p = atomicAdd(&g_cnt[d], 1);
        g_esrc[d * CAP + (p & (CAP - 1))] = s;   // mask: OOB-safe even if cap exceeded
    }
}

// ---------------------------------------------------------------------------
// Kernel 4: bucket aggregation + fused epilogue.
// 8 threads per node, each owns 8 columns (one uint4 = 8 halves per gather).
// fp32 accumulation; out = relu(acc * norm + bias).
// ---------------------------------------------------------------------------
__global__ __launch_bounds__(256)
void aggregate_kernel(const float* __restrict__ norm,
                      const float* __restrict__ bias,
                      float* __restrict__ out) {
    int gid = blockIdx.x * blockDim.x + threadIdx.x;  // 400000 threads
    int v = gid >> 3;
    int c = gid & 7;          // 8 col-groups of 8 cols
    if (v >= N_NODES) return;

    const int* el = g_esrc + (size_t)v * CAP;
    int deg = g_cnt[v];
    if (deg > CAP) deg = CAP;

    float acc[8];
    #pragma unroll
    for (int i = 0; i < 8; i++) acc[i] = 0.f;

    auto accum = [&](int s) {
        uint4 raw = *reinterpret_cast<const uint4*>(g_hw_h + (size_t)s * OUT_FEATS + c * 8);
        const __half2* hp = reinterpret_cast<const __half2*>(&raw);
        #pragma unroll
        for (int i = 0; i < 4; i++) {
            float2 f = __half22float2(hp[i]);
            acc[i * 2]     += f.x;
            acc[i * 2 + 1] += f.y;
        }
    };

    int j = 0;
    for (; j + 4 <= deg; j += 4) {
        int s0 = el[j], s1 = el[j + 1], s2 = el[j + 2], s3 = el[j + 3];
        accum(s0); accum(s1); accum(s2); accum(s3);
    }
    for (; j < deg; j++) accum(el[j]);

    float nv = norm[v];
    const float4* bp = reinterpret_cast<const float4*>(bias + c * 8);
    float4 b0 = bp[0], b1 = bp[1];
    float4 o0, o1;
    o0.x = fmaxf(fmaf(acc[0], nv, b0.x), 0.f);
    o0.y = fmaxf(fmaf(acc[1], nv, b0.y), 0.f);
    o0.z = fmaxf(fmaf(acc[2], nv, b0.z), 0.f);
    o0.w = fmaxf(fmaf(acc[3], nv, b0.w), 0.f);
    o1.x = fmaxf(fmaf(acc[4], nv, b1.x), 0.f);
    o1.y = fmaxf(fmaf(acc[5], nv, b1.y), 0.f);
    o1.z = fmaxf(fmaf(acc[6], nv, b1.z), 0.f);
    o1.w = fmaxf(fmaf(acc[7], nv, b1.w), 0.f);
    float4* op = reinterpret_cast<float4*>(out + (size_t)v * OUT_FEATS + c * 8);
    op[0] = o0;
    op[1] = o1;
}

// ---------------------------------------------------------------------------
// Launch: fork/join two independent pipelines inside graph capture.
//   stream 0 (capture origin): wconv -> gemm
//   side stream:               zero_cnt -> place
//   join -> aggregate
// ---------------------------------------------------------------------------
extern "C" void kernel_launch(void* const* d_in, const int* in_sizes, int n_in,
                              void* d_out, int out_size) {
    const float* h      = (const float*)d_in[0];   // [50000, 256]
    const float* norm   = (const float*)d_in[1];   // [50000, 1]
    const float* weight = (const float*)d_in[2];   // [256, 64]
    const float* bias   = (const float*)d_in[3];   // [64]
    const int*   src    = (const int*)d_in[4];     // [800000]
    const int*   dst    = (const int*)d_in[5];     // [800000]
    float* out = (float*)d_out;                    // [50000, 64]

    // One-time stream/event creation (first call is outside capture).
    static cudaStream_t s2 = nullptr;
    static cudaEvent_t  eFork = nullptr, eJoin = nullptr;
    if (!s2) {
        cudaStreamCreateWithFlags(&s2, cudaStreamNonBlocking);
        cudaEventCreateWithFlags(&eFork, cudaEventDisableTiming);
        cudaEventCreateWithFlags(&eJoin, cudaEventDisableTiming);
    }

    // Fork
    cudaEventRecord(eFork, 0);
    cudaStreamWaitEvent(s2, eFork, 0);

    // Branch A (legacy stream): weight conv + GEMM
    wconv_kernel<<<(IN_FEATS * OUT_FEATS / 4 + 255) / 256, 256>>>(weight);
    gemm_tf32_kernel<<<(N_NODES + 127) / 128, 256>>>(h, norm);

    // Branch B (side stream): counter zero + edge bucketing
    zero_cnt_kernel<<<(N_NODES + 255) / 256, 256, 0, s2>>>();
    place_kernel<<<(N_EDGES + 255) / 256, 256, 0, s2>>>(src, dst);

    // Join
    cudaEventRecord(eJoin, s2);
    cudaStreamWaitEvent(0, eJoin, 0);

    // Aggregate + fused epilogue
    aggregate_kernel<<<(N_NODES * 8 + 255) / 256, 256>>>(norm, bias, out);
}

// round 8
// speedup vs baseline: 1.0403x; 1.0403x over previous
#include <cuda_runtime.h>
#include <cuda_fp16.h>
#include <cstdint>

#define N_NODES   50000
#define N_EDGES   800000
#define IN_FEATS  256
#define OUT_FEATS 64
#define CAP       64          // bucket capacity; P(Poisson(16) > 64) ~ 2e-18/node
#define DUMMY     50000       // dummy src id -> all-zero row of g_hw_h

// Scratch (__device__ globals: no allocation allowed)
__device__ __half    g_hw_h[(N_NODES + 1) * OUT_FEATS]; // +1 zero dummy row
__device__ uint32_t  g_w_tf32[IN_FEATS * OUT_FEATS];    // W pre-converted to tf32
__device__ int       g_cnt[N_NODES];                    // per-dst degree counters
__device__ uint16_t  g_esrc16[N_NODES * CAP];           // bucketed src ids (6.4MB)

// ---------------------------------------------------------------------------
// Kernel 0: convert W -> tf32 (rna) once.
// ---------------------------------------------------------------------------
__global__ __launch_bounds__(256)
void wconv_kernel(const float* __restrict__ W) {
    int gid = blockIdx.x * blockDim.x + threadIdx.x;   // 4096 float4s
    if (gid < IN_FEATS * OUT_FEATS / 4) {
        float4 v = *reinterpret_cast<const float4*>(W + gid * 4);
        uint4 u;
        asm("cvt.rna.tf32.f32 %0, %1;" : "=r"(u.x) : "f"(v.x));
        asm("cvt.rna.tf32.f32 %0, %1;" : "=r"(u.y) : "f"(v.y));
        asm("cvt.rna.tf32.f32 %0, %1;" : "=r"(u.z) : "f"(v.z));
        asm("cvt.rna.tf32.f32 %0, %1;" : "=r"(u.w) : "f"(v.w));
        *reinterpret_cast<uint4*>(g_w_tf32 + gid * 4) = u;
    }
}

// ---------------------------------------------------------------------------
// Kernel 1: init -- zero counters, pre-fill buckets with DUMMY, zero dummy row.
// 400000 threads: one uint4 (8 ushorts) of g_esrc16 each.
// ---------------------------------------------------------------------------
__global__ __launch_bounds__(256)
void init_kernel() {
    int gid = blockIdx.x * blockDim.x + threadIdx.x;
    if (gid < N_NODES * CAP / 8) {
        uint4 f = make_uint4(0xC350C350u, 0xC350C350u, 0xC350C350u, 0xC350C350u); // 50000
        *reinterpret_cast<uint4*>(g_esrc16 + gid * 8) = f;
    }
    if (gid < N_NODES) g_cnt[gid] = 0;
    if (gid < OUT_FEATS / 8)  // zero dummy row (64 halves = 8 uint4)
        *reinterpret_cast<uint4*>(g_hw_h + (size_t)DUMMY * OUT_FEATS + gid * 8) =
            make_uint4(0u, 0u, 0u, 0u);
}

// ---------------------------------------------------------------------------
// Kernel 2: hw = (h @ W) * norm  -- tf32 mma.sync, cp.async double-buffered.
// ---------------------------------------------------------------------------
#define PAD_A 68
#define PAD_B 72

__device__ __forceinline__ uint32_t f2tf32(float f) {
    uint32_t u;
    asm("cvt.rna.tf32.f32 %0, %1;" : "=r"(u) : "f"(f));
    return u;
}

__device__ __forceinline__ void cp_async16(void* smem_dst, const void* gmem_src) {
    uint32_t s;
    asm("{ .reg .u64 t; cvta.to.shared.u64 t, %1; cvt.u32.u64 %0, t; }"
        : "=r"(s) : "l"(smem_dst));
    asm volatile("cp.async.cg.shared.global [%0], [%1], 16;" :: "r"(s), "l"(gmem_src));
}

__global__ __launch_bounds__(256)
void gemm_tf32_kernel(const float* __restrict__ h,
                      const float* __restrict__ norm) {
    __shared__ uint32_t shA[2][128 * PAD_A];   // raw fp32 bits
    __shared__ uint32_t shB[2][64 * PAD_B];    // tf32 bits

    const int tid  = threadIdx.x;
    const int warp = tid >> 5;
    const int lane = tid & 31;
    const int g    = lane >> 2;
    const int tg   = lane & 3;
    const int rowBase = blockIdx.x * 128;

    float acc[8][4];
    #pragma unroll
    for (int t = 0; t < 8; t++)
        #pragma unroll
        for (int i = 0; i < 4; i++) acc[t][i] = 0.f;

    auto stage = [&](int kk, int b) {
        #pragma unroll
        for (int j = 0; j < 8; j++) {
            int idx = tid + j * 256;
            int r   = idx >> 4;
            int k4  = idx & 15;
            int row = rowBase + r;
            if (row >= N_NODES) row = N_NODES - 1;     // clamp: junk computed, never stored
            cp_async16(&shA[b][r * PAD_A + k4 * 4],
                       h + (size_t)row * IN_FEATS + kk + k4 * 4);
        }
        #pragma unroll
        for (int j = 0; j < 4; j++) {
            int idx = tid + j * 256;
            int r   = idx >> 4;
            int k4  = idx & 15;
            cp_async16(&shB[b][r * PAD_B + k4 * 4],
                       g_w_tf32 + (size_t)(kk + r) * OUT_FEATS + k4 * 4);
        }
        asm volatile("cp.async.commit_group;" ::: "memory");
    };

    stage(0, 0);

    #pragma unroll
    for (int c = 0; c < 4; c++) {
        if (c < 3) stage((c + 1) * 64, (c + 1) & 1);
        if (c < 3) asm volatile("cp.async.wait_group 1;" ::: "memory");
        else       asm volatile("cp.async.wait_group 0;" ::: "memory");
        __syncthreads();

        const uint32_t* A = shA[c & 1];
        const uint32_t* B = shB[c & 1];
        const int ar = warp * 16;
        #pragma unroll
        for (int k8 = 0; k8 < 64; k8 += 8) {
            uint32_t a0 = f2tf32(__uint_as_float(A[(ar + g    ) * PAD_A + k8 + tg    ]));
            uint32_t a1 = f2tf32(__uint_as_float(A[(ar + g + 8) * PAD_A + k8 + tg    ]));
            uint32_t a2 = f2tf32(__uint_as_float(A[(ar + g    ) * PAD_A + k8 + tg + 4]));
            uint32_t a3 = f2tf32(__uint_as_float(A[(ar + g + 8) * PAD_A + k8 + tg + 4]));
            #pragma unroll
            for (int t = 0; t < 8; t++) {
                uint32_t b0 = B[(k8 + tg    ) * PAD_B + t * 8 + g];
                uint32_t b1 = B[(k8 + tg + 4) * PAD_B + t * 8 + g];
                asm volatile(
                    "mma.sync.aligned.m16n8k8.row.col.f32.tf32.tf32.f32 "
                    "{%0,%1,%2,%3}, {%4,%5,%6,%7}, {%8,%9}, {%0,%1,%2,%3};"
                    : "+f"(acc[t][0]), "+f"(acc[t][1]), "+f"(acc[t][2]), "+f"(acc[t][3])
                    : "r"(a0), "r"(a1), "r"(a2), "r"(a3), "r"(b0), "r"(b1));
            }
        }
        __syncthreads();
    }

    int r0 = rowBase + warp * 16 + g;
    int r1 = r0 + 8;
    if (r0 < N_NODES) {
        float nv = norm[r0];
        #pragma unroll
        for (int t = 0; t < 8; t++) {
            __half2 p = __floats2half2_rn(acc[t][0] * nv, acc[t][1] * nv);
            *reinterpret_cast<__half2*>(g_hw_h + (size_t)r0 * OUT_FEATS + t * 8 + tg * 2) = p;
        }
    }
    if (r1 < N_NODES) {
        float nv = norm[r1];
        #pragma unroll
        for (int t = 0; t < 8; t++) {
            __half2 p = __floats2half2_rn(acc[t][2] * nv, acc[t][3] * nv);
            *reinterpret_cast<__half2*>(g_hw_h + (size_t)r1 * OUT_FEATS + t * 8 + tg * 2) = p;
        }
    }
}

// ---------------------------------------------------------------------------
// Kernel 3: bucket placement, 1 edge per thread, uint16 src ids.
// ---------------------------------------------------------------------------
__global__ __launch_bounds__(256)
void place_kernel(const int* __restrict__ src, const int* __restrict__ dst) {
    int e = blockIdx.x * blockDim.x + threadIdx.x;
    if (e < N_EDGES) {
        int d = __ldg(dst + e);
        int s = __ldg(src + e);
        int p = atomicAdd(&g_cnt[d], 1);
        g_esrc16[d * CAP + (p & (CAP - 1))] = (uint16_t)s;  // masked: OOB-safe
    }
}

// ---------------------------------------------------------------------------
// Kernel 4: bucket aggregation + fused epilogue.
// 8 threads per node (8 fp16 cols = 16B each). Batch-8: one uint4 el load
// yields 8 ids -> 8 independent gathers (MLP=8). deg padded to multiple of 8
// with DUMMY entries hitting the hot zero row.
// ---------------------------------------------------------------------------
__global__ __launch_bounds__(256)
void aggregate_kernel(const float* __restrict__ norm,
                      const float* __restrict__ bias,
                      float* __restrict__ out) {
    int gid = blockIdx.x * blockDim.x + threadIdx.x;  // 400000 threads
    int v = gid >> 3;
    int c = gid & 7;
    if (v >= N_NODES) return;

    const uint16_t* el = g_esrc16 + (size_t)v * CAP;
    int deg = g_cnt[v];
    if (deg > CAP) deg = CAP;
    int padded = (deg + 7) & ~7;

    float acc[8];
    #pragma unroll
    for (int i = 0; i < 8; i++) acc[i] = 0.f;

    for (int base = 0; base < padded; base += 8) {
        uint4 ev = *reinterpret_cast<const uint4*>(el + base);  // 8 ids
        int id[8];
        id[0] = ev.x & 0xFFFF; id[1] = ev.x >> 16;
        id[2] = ev.y & 0xFFFF; id[3] = ev.y >> 16;
        id[4] = ev.z & 0xFFFF; id[5] = ev.z >> 16;
        id[6] = ev.w & 0xFFFF; id[7] = ev.w >> 16;

        uint4 raw[8];
        #pragma unroll
        for (int i = 0; i < 8; i++)
            raw[i] = *reinterpret_cast<const uint4*>(
                g_hw_h + (size_t)id[i] * OUT_FEATS + c * 8);

        #pragma unroll
        for (int i = 0; i < 8; i++) {
            const __half2* hp = reinterpret_cast<const __half2*>(&raw[i]);
            #pragma unroll
            for (int q = 0; q < 4; q++) {
                float2 f = __half22float2(hp[q]);
                acc[q * 2]     += f.x;
                acc[q * 2 + 1] += f.y;
            }
        }
    }

    float nv = norm[v];
    const float4* bp = reinterpret_cast<const float4*>(bias + c * 8);
    float4 b0 = bp[0], b1 = bp[1];
    float4 o0, o1;
    o0.x = fmaxf(fmaf(acc[0], nv, b0.x), 0.f);
    o0.y = fmaxf(fmaf(acc[1], nv, b0.y), 0.f);
    o0.z = fmaxf(fmaf(acc[2], nv, b0.z), 0.f);
    o0.w = fmaxf(fmaf(acc[3], nv, b0.w), 0.f);
    o1.x = fmaxf(fmaf(acc[4], nv, b1.x), 0.f);
    o1.y = fmaxf(fmaf(acc[5], nv, b1.y), 0.f);
    o1.z = fmaxf(fmaf(acc[6], nv, b1.z), 0.f);
    o1.w = fmaxf(fmaf(acc[7], nv, b1.w), 0.f);
    float4* op = reinterpret_cast<float4*>(out + (size_t)v * OUT_FEATS + c * 8);
    op[0] = o0;
    op[1] = o1;
}

// ---------------------------------------------------------------------------
// Launch: fork/join; bucket branch first, GEMM branch on side stream.
// ---------------------------------------------------------------------------
extern "C" void kernel_launch(void* const* d_in, const int* in_sizes, int n_in,
                              void* d_out, int out_size) {
    const float* h      = (const float*)d_in[0];   // [50000, 256]
    const float* norm   = (const float*)d_in[1];   // [50000, 1]
    const float* weight = (const float*)d_in[2];   // [256, 64]
    const float* bias   = (const float*)d_in[3];   // [64]
    const int*   src    = (const int*)d_in[4];     // [800000]
    const int*   dst    = (const int*)d_in[5];     // [800000]
    float* out = (float*)d_out;                    // [50000, 64]

    static cudaStream_t s2 = nullptr;
    static cudaEvent_t  eFork = nullptr, eJoin = nullptr;
    if (!s2) {
        cudaStreamCreateWithFlags(&s2, cudaStreamNonBlocking);
        cudaEventCreateWithFlags(&eFork, cudaEventDisableTiming);
        cudaEventCreateWithFlags(&eJoin, cudaEventDisableTiming);
    }

    // Fork
    cudaEventRecord(eFork, 0);
    cudaStreamWaitEvent(s2, eFork, 0);

    // Branch A (legacy stream): init + edge bucketing
    init_kernel<<<(N_NODES * CAP / 8 + 255) / 256, 256>>>();
    place_kernel<<<(N_EDGES + 255) / 256, 256>>>(src, dst);

    // Branch B (side stream): weight conv + GEMM
    wconv_kernel<<<(IN_FEATS * OUT_FEATS / 4 + 255) / 256, 256, 0, s2>>>(weight);
    gemm_tf32_kernel<<<(N_NODES + 127) / 128, 256, 0, s2>>>(h, norm);

    // Join
    cudaEventRecord(eJoin, s2);
    cudaStreamWaitEvent(0, eJoin, 0);

    // Aggregate + fused epilogue
    aggregate_kernel<<<(N_NODES * 8 + 255) / 256, 256>>>(norm, bias, out);
}

// round 9
// speedup vs baseline: 1.0927x; 1.0504x over previous
#include <cuda_runtime.h>
#include <cuda_fp16.h>
#include <cstdint>

#define N_NODES   50000
#define N_EDGES   800000
#define IN_FEATS  256
#define OUT_FEATS 64
#define CAP       64          // bucket capacity; P(Poisson(16) > 64) ~ 2e-18/node
#define DUMMY     50000       // dummy src id -> all-zero row of g_hw_h

// Scratch (__device__ globals: no allocation allowed)
__device__ __half    g_hw_h[(N_NODES + 1) * OUT_FEATS]; // +1 zero dummy row
__device__ uint32_t  g_w_tf32[IN_FEATS * OUT_FEATS];    // W pre-converted to tf32
__device__ int       g_cnt[N_NODES];                    // per-dst degree counters
__device__ uint16_t  g_esrc16[N_NODES * CAP];           // bucketed src ids (6.4MB)

// ---------------------------------------------------------------------------
// Kernel 0: fused init -- W->tf32 conversion, counter zero, bucket pre-fill,
// dummy-row zero. 400032 threads.
// ---------------------------------------------------------------------------
__global__ __launch_bounds__(256)
void init_kernel(const float* __restrict__ W) {
    int gid = blockIdx.x * blockDim.x + threadIdx.x;
    if (gid < N_NODES * CAP / 8) {
        uint4 f = make_uint4(0xC350C350u, 0xC350C350u, 0xC350C350u, 0xC350C350u); // 50000
        *reinterpret_cast<uint4*>(g_esrc16 + gid * 8) = f;
    }
    if (gid < N_NODES) g_cnt[gid] = 0;
    if (gid < OUT_FEATS / 8)  // zero dummy row
        *reinterpret_cast<uint4*>(g_hw_h + (size_t)DUMMY * OUT_FEATS + gid * 8) =
            make_uint4(0u, 0u, 0u, 0u);
    if (gid < IN_FEATS * OUT_FEATS / 4) {
        float4 v = *reinterpret_cast<const float4*>(W + gid * 4);
        uint4 u;
        asm("cvt.rna.tf32.f32 %0, %1;" : "=r"(u.x) : "f"(v.x));
        asm("cvt.rna.tf32.f32 %0, %1;" : "=r"(u.y) : "f"(v.y));
        asm("cvt.rna.tf32.f32 %0, %1;" : "=r"(u.z) : "f"(v.z));
        asm("cvt.rna.tf32.f32 %0, %1;" : "=r"(u.w) : "f"(v.w));
        *reinterpret_cast<uint4*>(g_w_tf32 + gid * 4) = u;
    }
}

// ---------------------------------------------------------------------------
// Kernel 1: hw = (h @ W) * norm  -- tf32 mma.sync, cp.async double-buffered.
// Tile 128x64, BK=32 (8 chunks), 256 threads. smem ~55KB -> 2 CTAs/SM.
// ---------------------------------------------------------------------------
#define PAD_A 36   // 32 + 4: bank stride 4 -> A-frag banks (4g+tg)%32 unique
#define PAD_B 72   // bank stride 8 -> B-frag banks (8tg+g)%32 unique

__device__ __forceinline__ uint32_t f2tf32(float f) {
    uint32_t u;
    asm("cvt.rna.tf32.f32 %0, %1;" : "=r"(u) : "f"(f));
    return u;
}

__device__ __forceinline__ void cp_async16(void* smem_dst, const void* gmem_src) {
    uint32_t s;
    asm("{ .reg .u64 t; cvta.to.shared.u64 t, %1; cvt.u32.u64 %0, t; }"
        : "=r"(s) : "l"(smem_dst));
    asm volatile("cp.async.cg.shared.global [%0], [%1], 16;" :: "r"(s), "l"(gmem_src));
}

__global__ __launch_bounds__(256, 2)
void gemm_tf32_kernel(const float* __restrict__ h,
                      const float* __restrict__ norm) {
    __shared__ uint32_t shA[2][128 * PAD_A];   // raw fp32 bits, 36.9KB
    __shared__ uint32_t shB[2][32 * PAD_B];    // tf32 bits,     18.4KB

    const int tid  = threadIdx.x;
    const int warp = tid >> 5;
    const int lane = tid & 31;
    const int g    = lane >> 2;
    const int tg   = lane & 3;
    const int rowBase = blockIdx.x * 128;

    float acc[8][4];
    #pragma unroll
    for (int t = 0; t < 8; t++)
        #pragma unroll
        for (int i = 0; i < 4; i++) acc[t][i] = 0.f;

    // stage one BK=32 chunk: A = 128x32 raw f32 (1024 f4), B = 32x64 tf32 (512 f4)
    auto stage = [&](int kk, int b) {
        #pragma unroll
        for (int j = 0; j < 4; j++) {
            int idx = tid + j * 256;       // 0..1023
            int r   = idx >> 3;            // 0..127
            int k4  = idx & 7;             // 0..7
            int row = rowBase + r;
            if (row >= N_NODES) row = N_NODES - 1;   // clamp: junk computed, never stored
            cp_async16(&shA[b][r * PAD_A + k4 * 4],
                       h + (size_t)row * IN_FEATS + kk + k4 * 4);
        }
        #pragma unroll
        for (int j = 0; j < 2; j++) {
            int idx = tid + j * 256;       // 0..511
            int r   = idx >> 4;            // 0..31
            int k4  = idx & 15;            // 0..15
            cp_async16(&shB[b][r * PAD_B + k4 * 4],
                       g_w_tf32 + (size_t)(kk + r) * OUT_FEATS + k4 * 4);
        }
        asm volatile("cp.async.commit_group;" ::: "memory");
    };

    stage(0, 0);

    #pragma unroll
    for (int c = 0; c < 8; c++) {          // 8 K-chunks of 32
        if (c < 7) stage((c + 1) * 32, (c + 1) & 1);
        if (c < 7) asm volatile("cp.async.wait_group 1;" ::: "memory");
        else       asm volatile("cp.async.wait_group 0;" ::: "memory");
        __syncthreads();

        const uint32_t* A = shA[c & 1];
        const uint32_t* B = shB[c & 1];
        const int ar = warp * 16;
        #pragma unroll
        for (int k8 = 0; k8 < 32; k8 += 8) {
            uint32_t a0 = f2tf32(__uint_as_float(A[(ar + g    ) * PAD_A + k8 + tg    ]));
            uint32_t a1 = f2tf32(__uint_as_float(A[(ar + g + 8) * PAD_A + k8 + tg    ]));
            uint32_t a2 = f2tf32(__uint_as_float(A[(ar + g    ) * PAD_A + k8 + tg + 4]));
            uint32_t a3 = f2tf32(__uint_as_float(A[(ar + g + 8) * PAD_A + k8 + tg + 4]));
            #pragma unroll
            for (int t = 0; t < 8; t++) {
                uint32_t b0 = B[(k8 + tg    ) * PAD_B + t * 8 + g];
                uint32_t b1 = B[(k8 + tg + 4) * PAD_B + t * 8 + g];
                asm volatile(
                    "mma.sync.aligned.m16n8k8.row.col.f32.tf32.tf32.f32 "
                    "{%0,%1,%2,%3}, {%4,%5,%6,%7}, {%8,%9}, {%0,%1,%2,%3};"
                    : "+f"(acc[t][0]), "+f"(acc[t][1]), "+f"(acc[t][2]), "+f"(acc[t][3])
                    : "r"(a0), "r"(a1), "r"(a2), "r"(a3), "r"(b0), "r"(b1));
            }
        }
        __syncthreads();
    }

    int r0 = rowBase + warp * 16 + g;
    int r1 = r0 + 8;
    if (r0 < N_NODES) {
        float nv = norm[r0];
        #pragma unroll
        for (int t = 0; t < 8; t++) {
            __half2 p = __floats2half2_rn(acc[t][0] * nv, acc[t][1] * nv);
            *reinterpret_cast<__half2*>(g_hw_h + (size_t)r0 * OUT_FEATS + t * 8 + tg * 2) = p;
        }
    }
    if (r1 < N_NODES) {
        float nv = norm[r1];
        #pragma unroll
        for (int t = 0; t < 8; t++) {
            __half2 p = __floats2half2_rn(acc[t][2] * nv, acc[t][3] * nv);
            *reinterpret_cast<__half2*>(g_hw_h + (size_t)r1 * OUT_FEATS + t * 8 + tg * 2) = p;
        }
    }
}

// ---------------------------------------------------------------------------
// Kernel 2: bucket placement, 1 edge per thread, uint16 src ids.
// ---------------------------------------------------------------------------
__global__ __launch_bounds__(256)
void place_kernel(const int* __restrict__ src, const int* __restrict__ dst) {
    int e = blockIdx.x * blockDim.x + threadIdx.x;
    if (e < N_EDGES) {
        int d = __ldg(dst + e);
        int s = __ldg(src + e);
        int p = atomicAdd(&g_cnt[d], 1);
        g_esrc16[d * CAP + (p & (CAP - 1))] = (uint16_t)s;  // masked: OOB-safe
    }
}

// ---------------------------------------------------------------------------
// Kernel 3: bucket aggregation + fused epilogue.
// 8 threads per node; batch-8 ids -> 8 independent 16B gathers (MLP=8);
// deg padded to multiple of 8 with DUMMY hitting the hot zero row.
// ---------------------------------------------------------------------------
__global__ __launch_bounds__(256)
void aggregate_kernel(const float* __restrict__ norm,
                      const float* __restrict__ bias,
                      float* __restrict__ out) {
    int gid = blockIdx.x * blockDim.x + threadIdx.x;  // 400000 threads
    int v = gid >> 3;
    int c = gid & 7;
    if (v >= N_NODES) return;

    const uint16_t* el = g_esrc16 + (size_t)v * CAP;
    int deg = g_cnt[v];
    if (deg > CAP) deg = CAP;
    int padded = (deg + 7) & ~7;

    float acc[8];
    #pragma unroll
    for (int i = 0; i < 8; i++) acc[i] = 0.f;

    for (int base = 0; base < padded; base += 8) {
        uint4 ev = *reinterpret_cast<const uint4*>(el + base);  // 8 ids
        int id[8];
        id[0] = ev.x & 0xFFFF; id[1] = ev.x >> 16;
        id[2] = ev.y & 0xFFFF; id[3] = ev.y >> 16;
        id[4] = ev.z & 0xFFFF; id[5] = ev.z >> 16;
        id[6] = ev.w & 0xFFFF; id[7] = ev.w >> 16;

        uint4 raw[8];
        #pragma unroll
        for (int i = 0; i < 8; i++)
            raw[i] = *reinterpret_cast<const uint4*>(
                g_hw_h + (size_t)id[i] * OUT_FEATS + c * 8);

        #pragma unroll
        for (int i = 0; i < 8; i++) {
            const __half2* hp = reinterpret_cast<const __half2*>(&raw[i]);
            #pragma unroll
            for (int q = 0; q < 4; q++) {
                float2 f = __half22float2(hp[q]);
                acc[q * 2]     += f.x;
                acc[q * 2 + 1] += f.y;
            }
        }
    }

    float nv = norm[v];
    const float4* bp = reinterpret_cast<const float4*>(bias + c * 8);
    float4 b0 = bp[0], b1 = bp[1];
    float4 o0, o1;
    o0.x = fmaxf(fmaf(acc[0], nv, b0.x), 0.f);
    o0.y = fmaxf(fmaf(acc[1], nv, b0.y), 0.f);
    o0.z = fmaxf(fmaf(acc[2], nv, b0.z), 0.f);
    o0.w = fmaxf(fmaf(acc[3], nv, b0.w), 0.f);
    o1.x = fmaxf(fmaf(acc[4], nv, b1.x), 0.f);
    o1.y = fmaxf(fmaf(acc[5], nv, b1.y), 0.f);
    o1.z = fmaxf(fmaf(acc[6], nv, b1.z), 0.f);
    o1.w = fmaxf(fmaf(acc[7], nv, b1.w), 0.f);
    float4* op = reinterpret_cast<float4*>(out + (size_t)v * OUT_FEATS + c * 8);
    op[0] = o0;
    op[1] = o1;
}

// ---------------------------------------------------------------------------
// Launch: fork/join. Main stream: init -> gemm. Side stream: place (after init).
// ---------------------------------------------------------------------------
extern "C" void kernel_launch(void* const* d_in, const int* in_sizes, int n_in,
                              void* d_out, int out_size) {
    const float* h      = (const float*)d_in[0];   // [50000, 256]
    const float* norm   = (const float*)d_in[1];   // [50000, 1]
    const float* weight = (const float*)d_in[2];   // [256, 64]
    const float* bias   = (const float*)d_in[3];   // [64]
    const int*   src    = (const int*)d_in[4];     // [800000]
    const int*   dst    = (const int*)d_in[5];     // [800000]
    float* out = (float*)d_out;                    // [50000, 64]

    static cudaStream_t s2 = nullptr;
    static cudaEvent_t  eFork = nullptr, eJoin = nullptr;
    if (!s2) {
        cudaStreamCreateWithFlags(&s2, cudaStreamNonBlocking);
        cudaEventCreateWithFlags(&eFork, cudaEventDisableTiming);
        cudaEventCreateWithFlags(&eJoin, cudaEventDisableTiming);
    }

    // init (produces g_w_tf32, zeroed counters, bucket fill) on main stream
    init_kernel<<<(N_NODES * CAP / 8 + 255) / 256, 256>>>(weight);

    // Fork: place branch depends only on init's counters/buckets
    cudaEventRecord(eFork, 0);
    cudaStreamWaitEvent(s2, eFork, 0);
    place_kernel<<<(N_EDGES + 255) / 256, 256, 0, s2>>>(src, dst);
    cudaEventRecord(eJoin, s2);

    // GEMM on main stream (overlaps place)
    gemm_tf32_kernel<<<(N_NODES + 127) / 128, 256>>>(h, norm);

    // Join, then aggregate
    cudaStreamWaitEvent(0, eJoin, 0);
    aggregate_kernel<<<(N_NODES * 8 + 255) / 256, 256>>>(norm, bias, out);
}

// round 10
// speedup vs baseline: 1.1956x; 1.0941x over previous
#include <cuda_runtime.h>
#include <cuda_fp16.h>
#include <cstdint>

#define N_NODES   50000
#define N_EDGES   800000
#define IN_FEATS  256
#define OUT_FEATS 64
#define CAP       64          // bucket capacity; P(Poisson(16) > 64) ~ 2e-18/node
#define DUMMY     50000       // dummy src id -> all-zero row of g_hw_h

// Scratch (__device__ globals: no allocation allowed)
__device__ __half    g_hw_h[(N_NODES + 1) * OUT_FEATS]; // +1 zero dummy row
__device__ uint32_t  g_w_tf32[IN_FEATS * OUT_FEATS];    // W pre-converted to tf32
__device__ int       g_cnt[N_NODES];                    // per-dst degree counters
__device__ uint16_t  g_esrc16[N_NODES * CAP];           // bucketed src ids (6.4MB)

// ---------------------------------------------------------------------------
// Kernel 0: fused init -- W->tf32, counter zero, bucket pre-fill, dummy row.
// ---------------------------------------------------------------------------
__global__ __launch_bounds__(256)
void init_kernel(const float* __restrict__ W) {
    int gid = blockIdx.x * blockDim.x + threadIdx.x;
    if (gid < N_NODES * CAP / 8) {
        uint4 f = make_uint4(0xC350C350u, 0xC350C350u, 0xC350C350u, 0xC350C350u); // 50000
        *reinterpret_cast<uint4*>(g_esrc16 + gid * 8) = f;
    }
    if (gid < N_NODES) g_cnt[gid] = 0;
    if (gid < OUT_FEATS / 8)
        *reinterpret_cast<uint4*>(g_hw_h + (size_t)DUMMY * OUT_FEATS + gid * 8) =
            make_uint4(0u, 0u, 0u, 0u);
    if (gid < IN_FEATS * OUT_FEATS / 4) {
        float4 v = *reinterpret_cast<const float4*>(W + gid * 4);
        uint4 u;
        asm("cvt.rna.tf32.f32 %0, %1;" : "=r"(u.x) : "f"(v.x));
        asm("cvt.rna.tf32.f32 %0, %1;" : "=r"(u.y) : "f"(v.y));
        asm("cvt.rna.tf32.f32 %0, %1;" : "=r"(u.z) : "f"(v.z));
        asm("cvt.rna.tf32.f32 %0, %1;" : "=r"(u.w) : "f"(v.w));
        *reinterpret_cast<uint4*>(g_w_tf32 + gid * 4) = u;
    }
}

// ---------------------------------------------------------------------------
// Kernel 1: hw = (h @ W) * norm  -- tf32 mma.sync, 3-stage cp.async pipeline.
// Tile 128x64, BK=32 (8 chunks), 256 threads. smem ~83KB -> 2 CTAs/SM.
// ---------------------------------------------------------------------------
#define PAD_A 36   // bank stride 4 -> A-frag banks (4g+tg)%32 unique
#define PAD_B 72   // bank stride 8 -> B-frag banks (8tg+g)%32 unique
#define STAGES 3

__device__ __forceinline__ uint32_t f2tf32(float f) {
    uint32_t u;
    asm("cvt.rna.tf32.f32 %0, %1;" : "=r"(u) : "f"(f));
    return u;
}

__device__ __forceinline__ void cp_async16(void* smem_dst, const void* gmem_src) {
    uint32_t s;
    asm("{ .reg .u64 t; cvta.to.shared.u64 t, %1; cvt.u32.u64 %0, t; }"
        : "=r"(s) : "l"(smem_dst));
    asm volatile("cp.async.cg.shared.global [%0], [%1], 16;" :: "r"(s), "l"(gmem_src));
}

__global__ __launch_bounds__(256, 2)
void gemm_tf32_kernel(const float* __restrict__ h,
                      const float* __restrict__ norm) {
    __shared__ uint32_t shA[STAGES][128 * PAD_A];   // raw fp32 bits, 55.3KB
    __shared__ uint32_t shB[STAGES][32 * PAD_B];    // tf32 bits,     27.6KB

    const int tid  = threadIdx.x;
    const int warp = tid >> 5;
    const int lane = tid & 31;
    const int g    = lane >> 2;
    const int tg   = lane & 3;
    const int rowBase = blockIdx.x * 128;

    float acc[8][4];
    #pragma unroll
    for (int t = 0; t < 8; t++)
        #pragma unroll
        for (int i = 0; i < 4; i++) acc[t][i] = 0.f;

    auto stage = [&](int kk, int b) {
        #pragma unroll
        for (int j = 0; j < 4; j++) {
            int idx = tid + j * 256;       // 0..1023
            int r   = idx >> 3;            // 0..127
            int k4  = idx & 7;             // 0..7
            int row = rowBase + r;
            if (row >= N_NODES) row = N_NODES - 1;   // clamp: junk computed, never stored
            cp_async16(&shA[b][r * PAD_A + k4 * 4],
                       h + (size_t)row * IN_FEATS + kk + k4 * 4);
        }
        #pragma unroll
        for (int j = 0; j < 2; j++) {
            int idx = tid + j * 256;       // 0..511
            int r   = idx >> 4;            // 0..31
            int k4  = idx & 15;            // 0..15
            cp_async16(&shB[b][r * PAD_B + k4 * 4],
                       g_w_tf32 + (size_t)(kk + r) * OUT_FEATS + k4 * 4);
        }
        asm volatile("cp.async.commit_group;" ::: "memory");
    };

    stage(0, 0);
    stage(32, 1);

    #pragma unroll
    for (int c = 0; c < 8; c++) {          // 8 K-chunks of 32
        if (c < 7) asm volatile("cp.async.wait_group 1;" ::: "memory");
        else       asm volatile("cp.async.wait_group 0;" ::: "memory");
        __syncthreads();
        if (c + 2 < 8) stage((c + 2) * 32, (c + 2) % STAGES);

        const uint32_t* A = shA[c % STAGES];
        const uint32_t* B = shB[c % STAGES];
        const int ar = warp * 16;
        #pragma unroll
        for (int k8 = 0; k8 < 32; k8 += 8) {
            uint32_t a0 = f2tf32(__uint_as_float(A[(ar + g    ) * PAD_A + k8 + tg    ]));
            uint32_t a1 = f2tf32(__uint_as_float(A[(ar + g + 8) * PAD_A + k8 + tg    ]));
            uint32_t a2 = f2tf32(__uint_as_float(A[(ar + g    ) * PAD_A + k8 + tg + 4]));
            uint32_t a3 = f2tf32(__uint_as_float(A[(ar + g + 8) * PAD_A + k8 + tg + 4]));
            #pragma unroll
            for (int t = 0; t < 8; t++) {
                uint32_t b0 = B[(k8 + tg    ) * PAD_B + t * 8 + g];
                uint32_t b1 = B[(k8 + tg + 4) * PAD_B + t * 8 + g];
                asm volatile(
                    "mma.sync.aligned.m16n8k8.row.col.f32.tf32.tf32.f32 "
                    "{%0,%1,%2,%3}, {%4,%5,%6,%7}, {%8,%9}, {%0,%1,%2,%3};"
                    : "+f"(acc[t][0]), "+f"(acc[t][1]), "+f"(acc[t][2]), "+f"(acc[t][3])
                    : "r"(a0), "r"(a1), "r"(a2), "r"(a3), "r"(b0), "r"(b1));
            }
        }
        __syncthreads();
    }

    int r0 = rowBase + warp * 16 + g;
    int r1 = r0 + 8;
    if (r0 < N_NODES) {
        float nv = norm[r0];
        #pragma unroll
        for (int t = 0; t < 8; t++) {
            __half2 p = __floats2half2_rn(acc[t][0] * nv, acc[t][1] * nv);
            *reinterpret_cast<__half2*>(g_hw_h + (size_t)r0 * OUT_FEATS + t * 8 + tg * 2) = p;
        }
    }
    if (r1 < N_NODES) {
        float nv = norm[r1];
        #pragma unroll
        for (int t = 0; t < 8; t++) {
            __half2 p = __floats2half2_rn(acc[t][2] * nv, acc[t][3] * nv);
            *reinterpret_cast<__half2*>(g_hw_h + (size_t)r1 * OUT_FEATS + t * 8 + tg * 2) = p;
        }
    }
}

// ---------------------------------------------------------------------------
// Kernel 2: bucket placement, 1 edge per thread, uint16 src ids.
// ---------------------------------------------------------------------------
__global__ __launch_bounds__(256)
void place_kernel(const int* __restrict__ src, const int* __restrict__ dst) {
    int e = blockIdx.x * blockDim.x + threadIdx.x;
    if (e < N_EDGES) {
        int d = __ldg(dst + e);
        int s = __ldg(src + e);
        int p = atomicAdd(&g_cnt[d], 1);
        g_esrc16[d * CAP + (p & (CAP - 1))] = (uint16_t)s;  // masked: OOB-safe
    }
}

// ---------------------------------------------------------------------------
// Kernel 3: bucket aggregation + fused epilogue (unchanged from R9).
// ---------------------------------------------------------------------------
__global__ __launch_bounds__(256)
void aggregate_kernel(const float* __restrict__ norm,
                      const float* __restrict__ bias,
                      float* __restrict__ out) {
    int gid = blockIdx.x * blockDim.x + threadIdx.x;  // 400000 threads
    int v = gid >> 3;
    int c = gid & 7;
    if (v >= N_NODES) return;

    const uint16_t* el = g_esrc16 + (size_t)v * CAP;
    int deg = g_cnt[v];
    if (deg > CAP) deg = CAP;
    int padded = (deg + 7) & ~7;

    float acc[8];
    #pragma unroll
    for (int i = 0; i < 8; i++) acc[i] = 0.f;

    for (int base = 0; base < padded; base += 8) {
        uint4 ev = *reinterpret_cast<const uint4*>(el + base);  // 8 ids
        int id[8];
        id[0] = ev.x & 0xFFFF; id[1] = ev.x >> 16;
        id[2] = ev.y & 0xFFFF; id[3] = ev.y >> 16;
        id[4] = ev.z & 0xFFFF; id[5] = ev.z >> 16;
        id[6] = ev.w & 0xFFFF; id[7] = ev.w >> 16;

        uint4 raw[8];
        #pragma unroll
        for (int i = 0; i < 8; i++)
            raw[i] = *reinterpret_cast<const uint4*>(
                g_hw_h + (size_t)id[i] * OUT_FEATS + c * 8);

        #pragma unroll
        for (int i = 0; i < 8; i++) {
            const __half2* hp = reinterpret_cast<const __half2*>(&raw[i]);
            #pragma unroll
            for (int q = 0; q < 4; q++) {
                float2 f = __half22float2(hp[q]);
                acc[q * 2]     += f.x;
                acc[q * 2 + 1] += f.y;
            }
        }
    }

    float nv = norm[v];
    const float4* bp = reinterpret_cast<const float4*>(bias + c * 8);
    float4 b0 = bp[0], b1 = bp[1];
    float4 o0, o1;
    o0.x = fmaxf(fmaf(acc[0], nv, b0.x), 0.f);
    o0.y = fmaxf(fmaf(acc[1], nv, b0.y), 0.f);
    o0.z = fmaxf(fmaf(acc[2], nv, b0.z), 0.f);
    o0.w = fmaxf(fmaf(acc[3], nv, b0.w), 0.f);
    o1.x = fmaxf(fmaf(acc[4], nv, b1.x), 0.f);
    o1.y = fmaxf(fmaf(acc[5], nv, b1.y), 0.f);
    o1.z = fmaxf(fmaf(acc[6], nv, b1.z), 0.f);
    o1.w = fmaxf(fmaf(acc[7], nv, b1.w), 0.f);
    float4* op = reinterpret_cast<float4*>(out + (size_t)v * OUT_FEATS + c * 8);
    op[0] = o0;
    op[1] = o1;
}

// ---------------------------------------------------------------------------
// Launch: canonical capture fork/join. Capture-origin stream holds only
// init and aggregate; BOTH branches live on side streams.
// ---------------------------------------------------------------------------
extern "C" void kernel_launch(void* const* d_in, const int* in_sizes, int n_in,
                              void* d_out, int out_size) {
    const float* h      = (const float*)d_in[0];   // [50000, 256]
    const float* norm   = (const float*)d_in[1];   // [50000, 1]
    const float* weight = (const float*)d_in[2];   // [256, 64]
    const float* bias   = (const float*)d_in[3];   // [64]
    const int*   src    = (const int*)d_in[4];     // [800000]
    const int*   dst    = (const int*)d_in[5];     // [800000]
    float* out = (float*)d_out;                    // [50000, 64]

    static cudaStream_t sA = nullptr, sB = nullptr;
    static cudaEvent_t  eFork = nullptr, eA = nullptr, eB = nullptr;
    if (!sA) {
        cudaStreamCreateWithFlags(&sA, cudaStreamNonBlocking);
        cudaStreamCreateWithFlags(&sB, cudaStreamNonBlocking);
        cudaEventCreateWithFlags(&eFork, cudaEventDisableTiming);
        cudaEventCreateWithFlags(&eA, cudaEventDisableTiming);
        cudaEventCreateWithFlags(&eB, cudaEventDisableTiming);
    }

    // init on capture-origin stream
    init_kernel<<<(N_NODES * CAP / 8 + 255) / 256, 256>>>(weight);

    // Fork to two side streams
    cudaEventRecord(eFork, 0);
    cudaStreamWaitEvent(sA, eFork, 0);
    cudaStreamWaitEvent(sB, eFork, 0);

    gemm_tf32_kernel<<<(N_NODES + 127) / 128, 256, 0, sA>>>(h, norm);
    place_kernel<<<(N_EDGES + 255) / 256, 256, 0, sB>>>(src, dst);

    cudaEventRecord(eA, sA);
    cudaEventRecord(eB, sB);

    // Join on capture-origin stream, then aggregate
    cudaStreamWaitEvent(0, eA, 0);
    cudaStreamWaitEvent(0, eB, 0);
    aggregate_kernel<<<(N_NODES * 8 + 255) / 256, 256>>>(norm, bias, out);
}